// round 14
// baseline (speedup 1.0000x reference)
#include <cuda_runtime.h>
#include <math.h>

// ---------------- scratch (device globals; no allocations allowed) -------------
#define BATCH 16
__device__ float  g_stem_out[BATCH*64*256*256];   // conv-stem output (NCHW)
__device__ float  g_f[BATCH*64*128*128];          // f after BN+relu+maxpool
__device__ float  g_h[BATCH*704*529];             // concat roialign features
__device__ float  g_c1[BATCH*64*441];             // conv1 output (21x21)
__device__ float  g_p1[BATCH*64*100];             // after bn1+relu+pool (10x10)
__device__ float  g_fcin[BATCH*2048];             // conv2+relu, flattened
__device__ float  g_fc1v[BATCH*128];              // fc1+relu
__device__ double g_psum[64*16];                  // per (c,b) partial BN sums
__device__ double g_psq [64*16];
__device__ float  g_sscale[64], g_sshift[64];
__device__ float  g_b1scale[64], g_b1shift[64];

// ---------------- packed f32x2 helpers -----------------------------------------
typedef unsigned long long u64;
__device__ __forceinline__ void ffma2(u64& d, u64 a, u64 b) {
    asm("fma.rn.f32x2 %0,%1,%2,%0;" : "+l"(d) : "l"(a), "l"(b));
}
__device__ __forceinline__ float2 unpack2(u64 v) {
    float2 r; asm("mov.b64 {%0,%1},%2;" : "=f"(r.x), "=f"(r.y) : "l"(v)); return r;
}

// ---------------- zero accumulators (needed every graph replay) ----------------
__global__ void k_zero() {
    int idx = blockIdx.x * 256 + threadIdx.x;
    if (idx < 1024) { g_psum[idx] = 0.0; g_psq[idx] = 0.0; }
    for (int i = idx; i < BATCH*64*441; i += gridDim.x * 256) g_c1[i] = 0.0f;
}

// ---------------- stem conv: 7x7 s2 p3, NHWC in -> NCHW out --------------------
// tile = 16 oc x 8 out-rows x 32 cols; thread = 4 oc x 4 cols.
// s_in holds DUPLICATED values (v,v) so FFMA2 broadcast operands load directly;
// weights load as ulonglong2 pairs (no mov.b64 packs anywhere in the mainloop).
__global__ __launch_bounds__(256) void k_stem_conv(const float* __restrict__ x,
                                                   const float* __restrict__ w) {
    __shared__ float s_in[3*21*144];  // [c][21][144], 138 floats (69 dup values)
    __shared__ float s_w[2352];       // [(c*7+kh)*7+kw][16 oc]
    __shared__ float s_red[8][8];     // per-warp stats partials
    const int tid = threadIdx.x;
    const int b   = blockIdx.z >> 2;
    const int oc0 = (blockIdx.z & 3) * 16;
    const int base_ih = blockIdx.y * 16 - 3;
    const int base_iw = blockIdx.x * 64 - 3;

    for (int i = tid; i < 3*21*69; i += 256) {
        int c = i % 3, t = i / 3, ww = t % 69, hh = t / 69;
        int ih = base_ih + hh, iw = base_iw + ww;
        float v = 0.0f;
        if ((unsigned)ih < 512u && (unsigned)iw < 512u)
            v = x[((b*512 + ih)*512 + iw)*3 + c];
        *(float2*)&s_in[(c*21 + hh)*144 + 2*ww] = make_float2(v, v);
    }
    for (int i = tid; i < 2352; i += 256) {
        int oc = i & 15, r = i >> 4;
        s_w[i] = w[(oc0 + oc)*147 + r];
    }
    __syncthreads();

    const int gx = tid & 7, gy = (tid >> 3) & 7, og = tid >> 6;
    // acc2[p][j]: oc pair (og*4+2p, og*4+2p+1), out col j
    u64 acc2[2][4];
#pragma unroll
    for (int p = 0; p < 2; p++)
#pragma unroll
        for (int j = 0; j < 4; j++) acc2[p][j] = 0ull;

#pragma unroll
    for (int c = 0; c < 3; c++)
#pragma unroll
    for (int kh = 0; kh < 7; kh++) {
        const float* rp = &s_in[(c*21 + 2*gy + kh)*144 + gx*16];
        u64 vv[14];
#pragma unroll
        for (int m = 0; m < 7; m++) {
            ulonglong2 q = *(const ulonglong2*)(rp + 4*m);
            vv[2*m]   = q.x;
            vv[2*m+1] = q.y;
        }
        const float* wp = &s_w[((c*7 + kh)*7)*16 + og*4];
#pragma unroll
        for (int kw = 0; kw < 7; kw++) {
            ulonglong2 wq = *(const ulonglong2*)(wp + kw*16);  // (w0,w1),(w2,w3)
#pragma unroll
            for (int j = 0; j < 4; j++) {
                ffma2(acc2[0][j], wq.x, vv[kw + 2*j]);
                ffma2(acc2[1][j], wq.y, vv[kw + 2*j]);
            }
        }
    }

    float accf[4][4];
#pragma unroll
    for (int p = 0; p < 2; p++)
#pragma unroll
        for (int j = 0; j < 4; j++) {
            float2 f2 = unpack2(acc2[p][j]);
            accf[2*p][j]   = f2.x;
            accf[2*p+1][j] = f2.y;
        }

    const int oh  = blockIdx.y*8 + gy;
    const int ow0 = blockIdx.x*32 + gx*4;
#pragma unroll
    for (int o = 0; o < 4; o++) {
        int base = ((b*64 + oc0 + og*4 + o)*256 + oh)*256 + ow0;
        float4 st = make_float4(accf[o][0], accf[o][1], accf[o][2], accf[o][3]);
        *(float4*)&g_stem_out[base] = st;
    }

    // fused BN stats
    float red[8];
#pragma unroll
    for (int o = 0; o < 4; o++) {
        float s = 0.0f, q = 0.0f;
#pragma unroll
        for (int j = 0; j < 4; j++) {
            float v = accf[o][j];
            s += v; q = fmaf(v, v, q);
        }
        red[o] = s; red[4 + o] = q;
    }
#pragma unroll
    for (int off = 16; off; off >>= 1)
#pragma unroll
        for (int r = 0; r < 8; r++)
            red[r] += __shfl_down_sync(0xffffffffu, red[r], off);
    const int lane = tid & 31, wid = tid >> 5;
    if (lane == 0)
#pragma unroll
        for (int r = 0; r < 8; r++) s_red[wid][r] = red[r];
    __syncthreads();
    if (tid < 32) {
        int g2 = tid >> 3;
        int r  = tid & 7;
        float v = s_red[2*g2][r] + s_red[2*g2+1][r];
        int oc = oc0 + g2*4 + (r & 3);
        if (r < 4) atomicAdd(&g_psum[oc*16 + b], (double)v);
        else       atomicAdd(&g_psq [oc*16 + b], (double)v);
    }
}

__global__ void k_stem_prepare(const float* __restrict__ g,
                               const float* __restrict__ bb) {
    int c = threadIdx.x;
    double s = 0.0, q = 0.0;
    for (int b = 0; b < 16; b++) { s += g_psum[c*16 + b]; q += g_psq[c*16 + b]; }
    double N = 1048576.0;
    double mean = s / N;
    double var  = q / N - mean*mean;
    float sc = g[c] * rsqrtf((float)var + 1e-5f);
    g_sscale[c] = sc;
    g_sshift[c] = bb[c] - (float)mean * sc;
}

// ---------------- BN apply + relu + maxpool 3x3 s2 p1 -> f ---------------------
__global__ __launch_bounds__(256) void k_stem_pool() {
    const int idx = blockIdx.x*256 + threadIdx.x;   // 16 * 64 * 128 * 128
    const int px = idx & 127;
    const int py = (idx >> 7) & 127;
    const int z  = idx >> 14;                       // b*64 + c
    const float sc = g_sscale[z & 63], sh = g_sshift[z & 63];
    const float* p = g_stem_out + (size_t)z*65536;
    const int iy0 = 2*py - 1, ix0 = 2*px - 1;
    float m = 0.0f;
#pragma unroll
    for (int dr = 0; dr < 3; dr++) {
        int iy = iy0 + dr;
        if (iy < 0) continue;
        const float* row = p + iy*256;
#pragma unroll
        for (int dc = 0; dc < 3; dc++) {
            int ix = ix0 + dc;
            if (ix < 0) continue;
            float v = fmaf(row[ix], sc, sh);
            m = fmaxf(m, v);
        }
    }
    g_f[idx] = fmaxf(m, 0.0f);
}

// ---------------- on-the-fly grid_sample (±5° rotation) ------------------------
__device__ __forceinline__ float gs_tap(const float* p, float yy, float xx) {
    bool v = (xx >= 0.0f) && (xx < 128.0f) && (yy >= 0.0f) && (yy < 128.0f);
    int xi = (int)fminf(fmaxf(xx, 0.0f), 127.0f);
    int yi = (int)fminf(fmaxf(yy, 0.0f), 127.0f);
    return v ? p[yi*128 + xi] : 0.0f;
}

__device__ __forceinline__ float gs_eval(const float* __restrict__ p, int t,
                                         int yy, int xx) {
    const float C0 = 0.99619469809174553f;
    const float S5 = 0.08715574274765817f;
    float gx = (2*xx + 1)*(1.0f/128.0f) - 1.0f;
    float gy = (2*yy + 1)*(1.0f/128.0f) - 1.0f;
    float sg = t ? -S5 : S5;
    float gxp =  C0*gx + sg*gy;
    float gyp = -sg*gx + C0*gy;
    float ix = ((gxp + 1.0f)*128.0f - 1.0f)*0.5f;
    float iy = ((gyp + 1.0f)*128.0f - 1.0f)*0.5f;
    float x0f = floorf(ix), y0f = floorf(iy);
    float lx = ix - x0f, ly = iy - y0f;
    return gs_tap(p, y0f,        x0f)        * (1.0f - lx)*(1.0f - ly)
         + gs_tap(p, y0f + 1.0f, x0f)        * (1.0f - lx)*ly
         + gs_tap(p, y0f,        x0f + 1.0f) * lx*(1.0f - ly)
         + gs_tap(p, y0f + 1.0f, x0f + 1.0f) * lx*ly;
}

// ---------------- roialign -> h (16, 704, 23, 23) ------------------------------
__global__ void k_roialign(const float* __restrict__ box) {
    int idx = blockIdx.x*256 + threadIdx.x;
    if (idx >= 64*529) return;
    const int c  = idx / 529;
    const int sp = idx % 529;
    const int ph = sp / 23, pw = sp % 23;
    const int combo = blockIdx.y, b = blockIdx.z;

    const bool direct = (combo < 7);
    int slot, choff, t = 0;
    if (direct) { slot = combo; choff = combo*64; }
    else {
        int k2 = combo - 7;
        t = k2 >> 1;
        slot = k2 & 1; choff = 448 + k2*64;
    }
    const float* bp = box + b*28 + slot*4;
    float x1 = bp[0]*0.25f, y1 = bp[1]*0.25f;
    float x2 = bp[2]*0.25f, y2 = bp[3]*0.25f;
    float bw = fmaxf(x2 - x1, 1.0f) / 23.0f;
    float bh = fmaxf(y2 - y1, 1.0f) / 23.0f;
    const float* p = g_f + (size_t)(b*64 + c)*16384;

    float acc = 0.0f;
#pragma unroll
    for (int oi = 0; oi < 2; oi++)
#pragma unroll
    for (int oj = 0; oj < 2; oj++) {
        float py = (float)ph + (oi*0.5f + 0.25f);
        float px = (float)pw + (oj*0.5f + 0.25f);
        float yv = y1 + py*bh;
        float xv = x1 + px*bw;
        bool empty = (yv < -1.0f) || (yv > 128.0f) || (xv < -1.0f) || (xv > 128.0f);
        float yc = fminf(fmaxf(yv, 0.0f), 127.0f);
        float xc = fminf(fmaxf(xv, 0.0f), 127.0f);
        float y0f = floorf(yc), x0f = floorf(xc);
        int yi = (int)y0f, xi = (int)x0f;
        int yi1 = min(yi + 1, 127), xi1 = min(xi + 1, 127);
        float ly = yc - y0f, lx = xc - x0f;
        float hy = 1.0f - ly, hx = 1.0f - lx;
        float v;
        if (direct) {
            v = p[yi*128  + xi ] * hy*hx + p[yi*128  + xi1] * hy*lx
              + p[yi1*128 + xi ] * ly*hx + p[yi1*128 + xi1] * ly*lx;
        } else {
            v = gs_eval(p, t, yi,  xi ) * hy*hx + gs_eval(p, t, yi,  xi1) * hy*lx
              + gs_eval(p, t, yi1, xi ) * ly*hx + gs_eval(p, t, yi1, xi1) * ly*lx;
        }
        acc += empty ? 0.0f : v;
    }
    g_h[((size_t)(b*704 + choff + c))*529 + sp] = acc * 0.25f;
}

// ---------------- conv1: 3x3 p0, 704->64, 23x23 -> 21x21 -----------------------
// dup-input smem + ulonglong2 weight pairs: zero packs in the mainloop.
__global__ __launch_bounds__(448) void k_conv1(const float* __restrict__ w) {
    __shared__ float s_in[8832];   // [8][23][48] duplicated (v,v)
    __shared__ float s_w[576];     // [(c8*9+kh*3+kw)][8 oc]
    const int tid = threadIdx.x;
    const int split = blockIdx.x, ocg = blockIdx.y, b = blockIdx.z;
    const int oc0 = ocg*8;
    const int y = tid / 21, x = tid % 21;
    const bool act = tid < 441;
    u64 acc2[4];
#pragma unroll
    for (int o = 0; o < 4; o++) acc2[o] = 0ull;

    for (int cc = split*352; cc < split*352 + 352; cc += 8) {
        __syncthreads();
        for (int i = tid; i < 8*529; i += 448) {
            int c8 = i / 529, r = i % 529;
            float v = g_h[((size_t)(b*704 + cc + c8))*529 + r];
            *(float2*)&s_in[(c8*23 + r/23)*48 + 2*(r%23)] = make_float2(v, v);
        }
        for (int i = tid; i < 576; i += 448) {
            int oc = i & 7, r = i >> 3;
            s_w[i] = w[(oc0 + oc)*6336 + (cc + r/9)*9 + r%9];
        }
        __syncthreads();
        if (act) {
#pragma unroll
            for (int c8 = 0; c8 < 8; c8++) {
#pragma unroll
                for (int kh = 0; kh < 3; kh++) {
                    const float* rp = &s_in[(c8*23 + y + kh)*48 + 2*x];
                    u64 vv0 = *(const u64*)(rp);
                    u64 vv1 = *(const u64*)(rp + 2);
                    u64 vv2 = *(const u64*)(rp + 4);
                    const float* wp = &s_w[(c8*9 + kh*3)*8];
#pragma unroll
                    for (int kw = 0; kw < 3; kw++) {
                        u64 v = (kw == 0) ? vv0 : (kw == 1) ? vv1 : vv2;
                        ulonglong2 wa = *(const ulonglong2*)(wp + kw*8);
                        ulonglong2 wb = *(const ulonglong2*)(wp + kw*8 + 4);
                        ffma2(acc2[0], wa.x, v);
                        ffma2(acc2[1], wa.y, v);
                        ffma2(acc2[2], wb.x, v);
                        ffma2(acc2[3], wb.y, v);
                    }
                }
            }
        }
    }
    if (act) {
#pragma unroll
        for (int o = 0; o < 4; o++) {
            float2 f2 = unpack2(acc2[o]);
            atomicAdd(&g_c1[((size_t)(b*64 + oc0 + 2*o    ))*441 + tid], f2.x);
            atomicAdd(&g_c1[((size_t)(b*64 + oc0 + 2*o + 1))*441 + tid], f2.y);
        }
    }
}

// ---------------- bn1 stats --------------------------------------------------
__global__ void k_bn1stats(const float* __restrict__ g, const float* __restrict__ bb) {
    const int c = blockIdx.x;
    float s = 0.0f, q = 0.0f;
    for (int i = threadIdx.x; i < 7056; i += 256) {
        int b = i / 441, sp = i % 441;
        float v = g_c1[((size_t)(b*64 + c))*441 + sp];
        s += v; q += v*v;
    }
#pragma unroll
    for (int off = 16; off; off >>= 1) {
        s += __shfl_down_sync(0xffffffffu, s, off);
        q += __shfl_down_sync(0xffffffffu, q, off);
    }
    __shared__ float w1[8], w2[8];
    int lane = threadIdx.x & 31, wid = threadIdx.x >> 5;
    if (lane == 0) { w1[wid] = s; w2[wid] = q; }
    __syncthreads();
    if (threadIdx.x == 0) {
        float ts = 0.0f, tq = 0.0f;
        for (int i = 0; i < 8; i++) { ts += w1[i]; tq += w2[i]; }
        float mean = ts / 7056.0f;
        float var  = tq / 7056.0f - mean*mean;
        float sc = g[c] * rsqrtf(var + 1e-5f);
        g_b1scale[c] = sc;
        g_b1shift[c] = bb[c] - mean*sc;
    }
}

// ---------------- bn1 apply + relu + maxpool 2x2 s2 ----------------------------
__global__ void k_pool2() {
    int idx = blockIdx.x*256 + threadIdx.x;
    if (idx >= BATCH*64*100) return;
    int b = idx / 6400, r = idx % 6400;
    int c = r / 100, sxy = r % 100;
    int y = sxy / 10, x = sxy % 10;
    float sc = g_b1scale[c], sh = g_b1shift[c];
    const float* p = g_c1 + (size_t)(b*64 + c)*441;
    float m = -1e30f;
#pragma unroll
    for (int dr = 0; dr < 2; dr++)
#pragma unroll
        for (int dc = 0; dc < 2; dc++) {
            float v = fmaxf(fmaf(p[(2*y + dr)*21 + 2*x + dc], sc, sh), 0.0f);
            m = fmaxf(m, v);
        }
    g_p1[idx] = m;
}

// ---------------- conv2: 3x3 p0, 64->32, 10x10 -> 8x8, +bias, relu ------------
__global__ void k_conv2(const float* __restrict__ w, const float* __restrict__ bias) {
    __shared__ float s_in[3200];   // [32][10][10]
    __shared__ float s_w[2304];    // [(c*9+t)][8 oc]
    const int tid = threadIdx.x;
    const int ocg = blockIdx.x, b = blockIdx.y;
    const int oc0 = ocg*8;
    const int s = tid & 63, og = tid >> 6;
    const int y = s >> 3, x = s & 7;
    float acc[2] = {0.0f, 0.0f};

    for (int cc = 0; cc < 64; cc += 32) {
        __syncthreads();
        for (int i = tid; i < 3200; i += 256)
            s_in[i] = g_p1[((size_t)(b*64 + cc))*100 + i];
        for (int i = tid; i < 2304; i += 256) {
            int oc = i & 7, r = i >> 3;
            s_w[i] = w[(oc0 + oc)*576 + (cc + r/9)*9 + r%9];
        }
        __syncthreads();
#pragma unroll 4
        for (int c = 0; c < 32; c++) {
#pragma unroll
            for (int kh = 0; kh < 3; kh++) {
                const float* rp = &s_in[(c*10 + y + kh)*10 + x];
                float v0 = rp[0], v1 = rp[1], v2 = rp[2];
                const float* wp = &s_w[(c*9 + kh*3)*8 + og*2];
                acc[0] = fmaf(wp[0],  v0, acc[0]); acc[1] = fmaf(wp[1],  v0, acc[1]);
                acc[0] = fmaf(wp[8],  v1, acc[0]); acc[1] = fmaf(wp[9],  v1, acc[1]);
                acc[0] = fmaf(wp[16], v2, acc[0]); acc[1] = fmaf(wp[17], v2, acc[1]);
            }
        }
    }
#pragma unroll
    for (int o = 0; o < 2; o++) {
        int oc = oc0 + og*2 + o;
        g_fcin[b*2048 + oc*64 + s] = fmaxf(acc[o] + bias[oc], 0.0f);
    }
}

// ---------------- fc1: (16,2048) x (128,2048)^T + b, relu ----------------------
__global__ void k_fc1(const float* __restrict__ w, const float* __restrict__ bias) {
    const int j = blockIdx.x;
    float acc[16];
#pragma unroll
    for (int b = 0; b < 16; b++) acc[b] = 0.0f;
    for (int k = threadIdx.x; k < 2048; k += 256) {
        float wv = w[j*2048 + k];
#pragma unroll
        for (int b = 0; b < 16; b++)
            acc[b] = fmaf(wv, g_fcin[b*2048 + k], acc[b]);
    }
#pragma unroll
    for (int off = 16; off; off >>= 1)
#pragma unroll
        for (int b = 0; b < 16; b++)
            acc[b] += __shfl_down_sync(0xffffffffu, acc[b], off);
    __shared__ float red[8][16];
    int lane = threadIdx.x & 31, wid = threadIdx.x >> 5;
    if (lane == 0)
#pragma unroll
        for (int b = 0; b < 16; b++) red[wid][b] = acc[b];
    __syncthreads();
    if (threadIdx.x < 16) {
        float sv = 0.0f;
        for (int wdx = 0; wdx < 8; wdx++) sv += red[wdx][threadIdx.x];
        g_fc1v[threadIdx.x*128 + j] = fmaxf(sv + bias[j], 0.0f);
    }
}

// ---------------- head + tanh --------------------------------------------------
__global__ void k_head(const float* __restrict__ w, const float* __restrict__ bias,
                       float* __restrict__ out) {
    int t = threadIdx.x;          // 192 threads
    int b = t / 12, j = t % 12;
    float s = bias[j];
    for (int k = 0; k < 128; k++)
        s = fmaf(g_fc1v[b*128 + k], w[j*128 + k], s);
    out[t] = tanhf(s);
}

// ---------------- launch -------------------------------------------------------
extern "C" void kernel_launch(void* const* d_in, const int* in_sizes, int n_in,
                              void* d_out, int out_size) {
    const float* x       = (const float*)d_in[0];
    const float* box     = (const float*)d_in[1];
    const float* stem_w  = (const float*)d_in[2];
    const float* stem_g  = (const float*)d_in[3];
    const float* stem_b  = (const float*)d_in[4];
    const float* conv1_w = (const float*)d_in[5];
    /* conv1_b (d_in[6]) cancels exactly inside batchnorm — unused */
    const float* bn1_g   = (const float*)d_in[7];
    const float* bn1_b   = (const float*)d_in[8];
    const float* conv2_w = (const float*)d_in[9];
    const float* conv2_b = (const float*)d_in[10];
    const float* fc1_w   = (const float*)d_in[11];
    const float* fc1_b   = (const float*)d_in[12];
    const float* head_w  = (const float*)d_in[13];
    const float* head_b  = (const float*)d_in[14];
    float* out = (float*)d_out;

    k_zero<<<512, 256>>>();
    k_stem_conv<<<dim3(8, 32, 64), 256>>>(x, stem_w);
    k_stem_prepare<<<1, 64>>>(stem_g, stem_b);
    k_stem_pool<<<65536, 256>>>();
    k_roialign<<<dim3(133, 11, 16), 256>>>(box);
    k_conv1<<<dim3(2, 8, 16), 448>>>(conv1_w);
    k_bn1stats<<<64, 256>>>(bn1_g, bn1_b);
    k_pool2<<<400, 256>>>();
    k_conv2<<<dim3(4, 16), 256>>>(conv2_w, conv2_b);
    k_fc1<<<128, 256>>>(fc1_w, fc1_b);
    k_head<<<1, 192>>>(head_w, head_b, out);
}